// round 13
// baseline (speedup 1.0000x reference)
#include <cuda_runtime.h>
#include <cuda_bf16.h>
#include <stdint.h>
#include <math.h>

#define H 128
#define KVDIM 256
#define ZDIM 512
#define NMAX 50000
#define EMAX 500000
#define BSTRIDE 136

// ---------------- scratch ------------------------------------------------------
__device__ float    g_hq[NMAX * H];
__device__ float    g_hk[NMAX * H];
__device__ float    g_hv[NMAX * H];
__device__ unsigned g_Zb[NMAX * (ZDIM / 2)];   // Z as packed bf16x2
__device__ float    g_P[NMAX * 6];
// CSR
__device__ int      g_cnt[NMAX];
__device__ int      g_off[NMAX + 1];
__device__ int      g_cur[NMAX];
__device__ int      g_perm[EMAX];
__device__ int      g_rows[EMAX];
__device__ int      g_cols[EMAX];
// sorted per-edge data
__device__ float    g_cds[EMAX * 9];
__device__ float    g_rads[EMAX * 6];
__device__ float    g_araw[EMAX];
__device__ float    g_cvs[EMAX * 3];
// folded weights
__device__ float    g_wkh[H * H];
__device__ float    g_wvh[H * H];
__device__ float    g_wkr6[6 * H];
__device__ float    g_wvr6[6 * H];
__device__ float    g_bk[H];
__device__ float    g_bv[H];
__device__ float    g_whz[H * ZDIM];
__device__ float    g_wvc16[6 * ZDIM];
__device__ float    g_bz[ZDIM];
// pre-transposed hi/lo bf16 weights for qkv tensor GEMM: [t][n][k] packed bf16x2
__device__ unsigned g_BhT[3 * 128 * 64];
__device__ unsigned g_BlT[3 * 128 * 64];
// pre-transposed bf16 whz for zgemm: [n][k] packed bf16x2
__device__ unsigned g_whzTb[ZDIM * 64];

// ---------------- helpers ------------------------------------------------------
__device__ __forceinline__ float silu_f(float x) {
    float t;
    asm("tanh.approx.f32 %0, %1;" : "=f"(t) : "f"(0.5f * x));
    return 0.5f * x * (1.f + t);
}
__device__ __forceinline__ unsigned bf16x2_of(float x0, float x1) {
    unsigned r;
    asm("cvt.rn.bf16x2.f32 %0, %1, %2;" : "=r"(r) : "f"(x1), "f"(x0));
    return r;
}
__device__ __forceinline__ void mma_bf16(float c[4], uint32_t a0, uint32_t a1,
                                         uint32_t a2, uint32_t a3, uint32_t b0,
                                         uint32_t b1) {
    asm volatile(
        "mma.sync.aligned.m16n8k16.row.col.f32.bf16.bf16.f32 "
        "{%0,%1,%2,%3}, {%4,%5,%6,%7}, {%8,%9}, {%0,%1,%2,%3};"
        : "+f"(c[0]), "+f"(c[1]), "+f"(c[2]), "+f"(c[3])
        : "r"(a0), "r"(a1), "r"(a2), "r"(a3), "r"(b0), "r"(b1));
}
__device__ __forceinline__ int sym_a(int u) { return (u < 3) ? 0 : ((u < 5) ? 1 : 2); }
__device__ __forceinline__ int sym_b(int u) { return (u < 3) ? u : ((u < 5) ? (u - 2) : 2); }

// ---------------- CSR build ----------------------------------------------------
__global__ void zero_kernel(int N) {
    int i = blockIdx.x * blockDim.x + threadIdx.x;
    if (i < N) g_cnt[i] = 0;
}
__global__ void hist_kernel(const int* __restrict__ row, int E) {
    int e = blockIdx.x * blockDim.x + threadIdx.x;
    if (e < E) atomicAdd(&g_cnt[row[e]], 1);
}
__global__ void scan_kernel(int N) {
    __shared__ int part[1024];
    int tid = threadIdx.x;
    int chunk = (N + 1023) / 1024;
    int s = tid * chunk;
    int e = min(s + chunk, N);
    int sum = 0;
    for (int i = s; i < e; i++) sum += g_cnt[i];
    part[tid] = sum;
    __syncthreads();
    for (int off = 1; off < 1024; off *= 2) {
        int v = (tid >= off) ? part[tid - off] : 0;
        __syncthreads();
        part[tid] += v;
        __syncthreads();
    }
    int run = tid ? part[tid - 1] : 0;
    for (int i = s; i < e; i++) {
        g_off[i] = run;
        g_cur[i] = run;
        run += g_cnt[i];
    }
    if (tid == 1023) g_off[N] = part[1023];
}
__global__ void scatter_kernel(const int* __restrict__ row,
                               const int* __restrict__ col, int E) {
    int e = blockIdx.x * blockDim.x + threadIdx.x;
    if (e >= E) return;
    int r = row[e];
    int pos = atomicAdd(&g_cur[r], 1);
    g_perm[pos] = e;
    g_rows[pos] = r;
    g_cols[pos] = col[e];
}

// ---------------- weight folds -------------------------------------------------
__global__ void fold1_kernel(const float* __restrict__ Wkv,
                             const float* __restrict__ bkv) {
    int idx = blockIdx.x * blockDim.x + threadIdx.x;
    if (idx < H * H) {
        int t = idx >> 7, m = idx & 127;
        g_wkh[idx] = Wkv[(9 + t) * KVDIM + 2 * m];
        g_wvh[idx] = Wkv[(9 + t) * KVDIM + 2 * m + 1];
    }
    if (idx < 6 * H) {
        int u = idx >> 7, m = idx & 127;
        int a = sym_a(u), b = sym_b(u);
        int i1 = a * 3 + b, i2 = b * 3 + a;
        float k = Wkv[i1 * KVDIM + 2 * m];
        float v = Wkv[i1 * KVDIM + 2 * m + 1];
        if (i1 != i2) {
            k += Wkv[i2 * KVDIM + 2 * m];
            v += Wkv[i2 * KVDIM + 2 * m + 1];
        }
        g_wkr6[idx] = k;
        g_wvr6[idx] = v;
    }
    if (idx < H) {
        g_bk[idx] = bkv[2 * idx];
        g_bv[idx] = bkv[2 * idx + 1];
    }
}
__global__ void fold2_kernel(const float* __restrict__ Wc1) {
    int idx = blockIdx.x * blockDim.x + threadIdx.x;
    if (idx >= 135 * ZDIM) return;
    int t = idx / ZDIM, j = idx % ZDIM;
    const float* arow;
    if (t < 128) arow = &g_wvh[t * H];
    else if (t < 134) arow = &g_wvr6[(t - 128) * H];
    else arow = g_bv;
    float acc = 0.f;
#pragma unroll 8
    for (int m = 0; m < H; m++) acc += arow[m] * Wc1[(size_t)m * ZDIM + j];
    if (t < 128) g_whz[t * ZDIM + j] = acc;
    else if (t < 134) g_wvc16[(t - 128) * ZDIM + j] = acc;
    else g_bz[j] = acc;
}
// fold3: transpose + hi/lo-split Wq / wkh / wvh (needs fold1)
__global__ void fold3_kernel(const float* __restrict__ Wq) {
    int idx = blockIdx.x * blockDim.x + threadIdx.x;
    if (idx >= 3 * 128 * 64) return;
    int t = idx / 8192, rem = idx % 8192;
    int n = rem >> 6, k2 = rem & 63;
    const float* B = (t == 0) ? Wq : ((t == 1) ? g_wkh : g_wvh);
    float v0 = B[(size_t)(2 * k2) * H + n];
    float v1 = B[(size_t)(2 * k2 + 1) * H + n];
    unsigned hi = bf16x2_of(v0, v1);
    float h0 = __uint_as_float(hi << 16);
    float h1 = __uint_as_float(hi & 0xffff0000u);
    g_BhT[idx] = hi;
    g_BlT[idx] = bf16x2_of(v0 - h0, v1 - h1);
}
// fold4: transpose + bf16-pack whz for zgemm (needs fold2)
__global__ void fold4_kernel() {
    int idx = blockIdx.x * blockDim.x + threadIdx.x;
    if (idx >= ZDIM * 64) return;
    int n = idx >> 6, k2 = idx & 63;
    float v0 = g_whz[(size_t)(2 * k2) * ZDIM + n];
    float v1 = g_whz[(size_t)(2 * k2 + 1) * ZDIM + n];
    g_whzTb[idx] = bf16x2_of(v0, v1);
}

// ---------------- split-bf16 tensor GEMM for hq/hk/hv -------------------------
__global__ __launch_bounds__(256) void qkv_gemm(const float* __restrict__ h,
                                                const float* __restrict__ bq,
                                                int N) {
    extern __shared__ unsigned short qsm[];
    unsigned short* Ah = qsm;                    // [128][BSTRIDE]
    unsigned short* Al = Ah + 128 * BSTRIDE;
    unsigned short* Bh = Al + 128 * BSTRIDE;     // [n][k]
    unsigned short* Bl = Bh + 128 * BSTRIDE;

    int tid = threadIdx.x;
    int wid = tid >> 5, lane = tid & 31;
    int gid = lane >> 2, tig = lane & 3;
    int n0 = blockIdx.x * 128;
    int y = blockIdx.y;

    const float* bias;
    float* C;
    if (y == 0)      { bias = bq;   C = g_hq; }
    else if (y == 1) { bias = g_bk; C = g_hk; }
    else             { bias = g_bv; C = g_hv; }

    for (int idx = tid; idx < 128 * 64; idx += 256) {
        int row = idx >> 6, j = idx & 63;
        float2 f = make_float2(0.f, 0.f);
        if (n0 + row < N) f = *(const float2*)&h[(size_t)(n0 + row) * H + 2 * j];
        unsigned hi2 = bf16x2_of(f.x, f.y);
        float hx = __uint_as_float(hi2 << 16);
        float hy = __uint_as_float(hi2 & 0xffff0000u);
        unsigned lo2 = bf16x2_of(f.x - hx, f.y - hy);
        *(unsigned*)&Ah[row * BSTRIDE + 2 * j] = hi2;
        *(unsigned*)&Al[row * BSTRIDE + 2 * j] = lo2;
    }
    {
        const unsigned* bh = &g_BhT[y * 8192];
        const unsigned* bl = &g_BlT[y * 8192];
        for (int idx = tid; idx < 128 * 64; idx += 256) {
            int n = idx >> 6, k2 = idx & 63;
            *(unsigned*)&Bh[n * BSTRIDE + 2 * k2] = bh[idx];
            *(unsigned*)&Bl[n * BSTRIDE + 2 * k2] = bl[idx];
        }
    }
    __syncthreads();

    int wm = (wid & 3) * 32;
    int wn = (wid >> 2) * 64;

    float c[2][8][4];
#pragma unroll
    for (int mt = 0; mt < 2; mt++)
#pragma unroll
        for (int ntl = 0; ntl < 8; ntl++)
#pragma unroll
            for (int q = 0; q < 4; q++) c[mt][ntl][q] = 0.f;

#pragma unroll
    for (int k0 = 0; k0 < 128; k0 += 16) {
        uint32_t ah[2][4], al[2][4];
#pragma unroll
        for (int mt = 0; mt < 2; mt++) {
            int row = wm + mt * 16;
            int o0 = (row + gid) * BSTRIDE + k0 + 2 * tig;
            int o1 = (row + gid + 8) * BSTRIDE + k0 + 2 * tig;
            ah[mt][0] = *(const unsigned*)&Ah[o0];
            ah[mt][1] = *(const unsigned*)&Ah[o1];
            ah[mt][2] = *(const unsigned*)&Ah[o0 + 8];
            ah[mt][3] = *(const unsigned*)&Ah[o1 + 8];
            al[mt][0] = *(const unsigned*)&Al[o0];
            al[mt][1] = *(const unsigned*)&Al[o1];
            al[mt][2] = *(const unsigned*)&Al[o0 + 8];
            al[mt][3] = *(const unsigned*)&Al[o1 + 8];
        }
#pragma unroll
        for (int ntl = 0; ntl < 8; ntl++) {
            int col = wn + ntl * 8 + gid;
            int ob = col * BSTRIDE + k0 + 2 * tig;
            uint32_t bh0 = *(const unsigned*)&Bh[ob];
            uint32_t bh1 = *(const unsigned*)&Bh[ob + 8];
            uint32_t bl0 = *(const unsigned*)&Bl[ob];
            uint32_t bl1 = *(const unsigned*)&Bl[ob + 8];
#pragma unroll
            for (int mt = 0; mt < 2; mt++) {
                mma_bf16(c[mt][ntl], ah[mt][0], ah[mt][1], ah[mt][2], ah[mt][3],
                         bh0, bh1);
                mma_bf16(c[mt][ntl], ah[mt][0], ah[mt][1], ah[mt][2], ah[mt][3],
                         bl0, bl1);
                mma_bf16(c[mt][ntl], al[mt][0], al[mt][1], al[mt][2], al[mt][3],
                         bh0, bh1);
            }
        }
    }

#pragma unroll
    for (int mt = 0; mt < 2; mt++) {
        int r0 = n0 + wm + mt * 16 + gid;
#pragma unroll
        for (int ntl = 0; ntl < 8; ntl++) {
            int gcol = wn + ntl * 8 + 2 * tig;
            float b0 = bias[gcol], b1 = bias[gcol + 1];
            if (r0 < N)
                *(float2*)&C[(size_t)r0 * H + gcol] =
                    make_float2(c[mt][ntl][0] + b0, c[mt][ntl][1] + b1);
            if (r0 + 8 < N)
                *(float2*)&C[(size_t)(r0 + 8) * H + gcol] =
                    make_float2(c[mt][ntl][2] + b0, c[mt][ntl][3] + b1);
        }
    }
}

// ---------------- mma.sync bf16 Z GEMM: Zb = bf16(h @ whz + bz) ---------------
__global__ __launch_bounds__(256) void zgemm_kernel(const float* __restrict__ h,
                                                    int N) {
    extern __shared__ unsigned short zsm[];
    unsigned short* As = zsm;                  // [128][BSTRIDE]
    unsigned short* Bs = zsm + 128 * BSTRIDE;  // [n][k]

    int tid = threadIdx.x;
    int wid = tid >> 5, lane = tid & 31;
    int gid = lane >> 2, tig = lane & 3;
    int n0 = blockIdx.x * 128;
    int nt = blockIdx.y * 128;

    for (int idx = tid; idx < 128 * 64; idx += 256) {
        int row = idx >> 6, j = idx & 63;
        float2 f = make_float2(0.f, 0.f);
        if (n0 + row < N) f = *(const float2*)&h[(size_t)(n0 + row) * H + 2 * j];
        *(unsigned*)&As[row * BSTRIDE + 2 * j] = bf16x2_of(f.x, f.y);
    }
    {
        const unsigned* bsrc = &g_whzTb[(size_t)nt * 64];
        for (int idx = tid; idx < 128 * 64; idx += 256) {
            int n = idx >> 6, k2 = idx & 63;
            *(unsigned*)&Bs[n * BSTRIDE + 2 * k2] = bsrc[idx];
        }
    }
    __syncthreads();

    int wm = (wid & 3) * 32;
    int wn = (wid >> 2) * 64;

    float c[2][8][4];
#pragma unroll
    for (int mt = 0; mt < 2; mt++)
#pragma unroll
        for (int ntl = 0; ntl < 8; ntl++)
#pragma unroll
            for (int q = 0; q < 4; q++) c[mt][ntl][q] = 0.f;

#pragma unroll
    for (int k0 = 0; k0 < 128; k0 += 16) {
        uint32_t a[2][4];
#pragma unroll
        for (int mt = 0; mt < 2; mt++) {
            int row = wm + mt * 16;
            a[mt][0] = *(const unsigned*)&As[(row + gid) * BSTRIDE + k0 + 2 * tig];
            a[mt][1] = *(const unsigned*)&As[(row + gid + 8) * BSTRIDE + k0 + 2 * tig];
            a[mt][2] = *(const unsigned*)&As[(row + gid) * BSTRIDE + k0 + 2 * tig + 8];
            a[mt][3] = *(const unsigned*)&As[(row + gid + 8) * BSTRIDE + k0 + 2 * tig + 8];
        }
        uint32_t b[8][2];
#pragma unroll
        for (int ntl = 0; ntl < 8; ntl++) {
            int col = wn + ntl * 8 + gid;
            b[ntl][0] = *(const unsigned*)&Bs[col * BSTRIDE + k0 + 2 * tig];
            b[ntl][1] = *(const unsigned*)&Bs[col * BSTRIDE + k0 + 2 * tig + 8];
        }
#pragma unroll
        for (int mt = 0; mt < 2; mt++)
#pragma unroll
            for (int ntl = 0; ntl < 8; ntl++)
                mma_bf16(c[mt][ntl], a[mt][0], a[mt][1], a[mt][2], a[mt][3],
                         b[ntl][0], b[ntl][1]);
    }

#pragma unroll
    for (int mt = 0; mt < 2; mt++) {
        int r0 = n0 + wm + mt * 16 + gid;
#pragma unroll
        for (int ntl = 0; ntl < 8; ntl++) {
            int gcol = nt + wn + ntl * 8 + 2 * tig;
            float bz0 = g_bz[gcol], bz1 = g_bz[gcol + 1];
            if (r0 < N)
                g_Zb[(size_t)r0 * (ZDIM / 2) + (gcol >> 1)] =
                    bf16x2_of(c[mt][ntl][0] + bz0, c[mt][ntl][1] + bz1);
            if (r0 + 8 < N)
                g_Zb[(size_t)(r0 + 8) * (ZDIM / 2) + (gcol >> 1)] =
                    bf16x2_of(c[mt][ntl][2] + bz0, c[mt][ntl][3] + bz1);
        }
    }
}

// ---------------- P6: warp per node -------------------------------------------
__global__ void p_kernel(int N) {
    int r = (int)((blockIdx.x * blockDim.x + threadIdx.x) >> 5);
    int lane = threadIdx.x & 31;
    if (r >= N) return;
    float4 q = *(const float4*)&g_hq[(size_t)r * H + lane * 4];
#pragma unroll
    for (int u = 0; u < 6; u++) {
        float4 w = *(const float4*)&g_wkr6[u * H + lane * 4];
        float s = q.x * w.x + q.y * w.y + q.z * w.z + q.w * w.w;
#pragma unroll
        for (int o = 16; o; o >>= 1) s += __shfl_xor_sync(0xffffffffu, s, o);
        if (lane == 0) g_P[r * 6 + u] = s;
    }
}

// ---------------- fused edge kernel: prep (cd/rad/alpha) + cv -----------------
__global__ __launch_bounds__(256) void edge_kernel(const float* __restrict__ Wc2,
                                                   const float* __restrict__ coord,
                                                   int E) {
    int tid = threadIdx.x;
    int lane = tid & 31;
    int wg = (int)((blockIdx.x * blockDim.x + tid) >> 5);
    int e0 = wg * 8;
    if (e0 >= E) return;

    int cl[8];
    float rr[8];
#pragma unroll
    for (int g = 0; g < 8; g++) {
        int e = e0 + g;
        bool ok = (e < E);
        int r = ok ? g_rows[e] : 0;
        cl[g] = ok ? g_cols[e] : 0;
        float cdv = 0.f;
        if (lane < 9)
            cdv = coord[(size_t)r * 9 + lane] - coord[(size_t)cl[g] * 9 + lane];
        if (ok && lane < 9) g_cds[(size_t)e * 9 + lane] = cdv;
        float cd[9];
#pragma unroll
        for (int i = 0; i < 9; i++) cd[i] = __shfl_sync(0xffffffffu, cdv, i);
        float radv = 0.f;
        if (lane < 6) {
            int a = sym_a(lane), b = sym_b(lane);
            radv = cd[a * 3] * cd[b * 3] + cd[a * 3 + 1] * cd[b * 3 + 1] +
                   cd[a * 3 + 2] * cd[b * 3 + 2];
            if (ok) g_rads[(size_t)e * 6 + lane] = radv;
        }
        rr[g] = ok ? radv : 0.f;
        // alpha logit
        float4 q = *(const float4*)&g_hq[(size_t)r * H + lane * 4];
        float4 k = *(const float4*)&g_hk[(size_t)cl[g] * H + lane * 4];
        float ap = q.x * k.x + q.y * k.y + q.z * k.z + q.w * k.w;
        if (lane < 6) ap += radv * g_P[r * 6 + lane];
#pragma unroll
        for (int o = 16; o; o >>= 1) ap += __shfl_xor_sync(0xffffffffu, ap, o);
        if (ok && lane == 0) g_araw[e] = ap;
    }

    // ---- cv phase ----
    float pacc[8][3];
#pragma unroll
    for (int g = 0; g < 8; g++) pacc[g][0] = pacc[g][1] = pacc[g][2] = 0.f;

    for (int jc = 0; jc < 4; jc++) {
        int j0 = jc * 128 + lane * 4;
        float wv[6][4];
#pragma unroll
        for (int u = 0; u < 6; u++) {
            float4 f = *(const float4*)&g_wvc16[u * ZDIM + j0];
            wv[u][0] = f.x; wv[u][1] = f.y; wv[u][2] = f.z; wv[u][3] = f.w;
        }
        float w2[4][3];
#pragma unroll
        for (int jj = 0; jj < 4; jj++)
#pragma unroll
            for (int d = 0; d < 3; d++) w2[jj][d] = Wc2[(j0 + jj) * 3 + d];

#pragma unroll
        for (int g = 0; g < 8; g++) {
            uint2 z = *(const uint2*)&g_Zb[(size_t)cl[g] * (ZDIM / 2) + (j0 >> 1)];
            float x0 = __uint_as_float(z.x << 16);
            float x1 = __uint_as_float(z.x & 0xffff0000u);
            float x2 = __uint_as_float(z.y << 16);
            float x3 = __uint_as_float(z.y & 0xffff0000u);
#pragma unroll
            for (int u = 0; u < 6; u++) {
                float ri = __shfl_sync(0xffffffffu, rr[g], u);
                x0 += ri * wv[u][0];
                x1 += ri * wv[u][1];
                x2 += ri * wv[u][2];
                x3 += ri * wv[u][3];
            }
            float u0 = silu_f(x0), u1 = silu_f(x1), u2 = silu_f(x2), u3 = silu_f(x3);
#pragma unroll
            for (int d = 0; d < 3; d++)
                pacc[g][d] += u0 * w2[0][d] + u1 * w2[1][d] + u2 * w2[2][d] +
                              u3 * w2[3][d];
        }
    }
#pragma unroll
    for (int g = 0; g < 8; g++) {
        float p0 = pacc[g][0], p1 = pacc[g][1], p2 = pacc[g][2];
#pragma unroll
        for (int o = 16; o; o >>= 1) {
            p0 += __shfl_xor_sync(0xffffffffu, p0, o);
            p1 += __shfl_xor_sync(0xffffffffu, p1, o);
            p2 += __shfl_xor_sync(0xffffffffu, p2, o);
        }
        if (lane == 0 && e0 + g < E) {
            g_cvs[(size_t)(e0 + g) * 3 + 0] = p0;
            g_cvs[(size_t)(e0 + g) * 3 + 1] = p1;
            g_cvs[(size_t)(e0 + g) * 3 + 2] = p2;
        }
    }
}

// ---------------- row kernel: softmax + agg + finalize ------------------------
__global__ __launch_bounds__(256) void row_kernel(
    const float* __restrict__ h, const float* __restrict__ coord,
    float* __restrict__ out, float* __restrict__ alpha_out, int N) {
    __shared__ float wvr6_s[6 * H];
    int tid = threadIdx.x, lane = tid & 31, w = tid >> 5;
    for (int i = tid; i < 6 * H; i += 256) wvr6_s[i] = g_wvr6[i];
    __syncthreads();
    int r = blockIdx.x * 8 + w;
    if (r >= N) return;
    int s = g_off[r], e = g_off[r + 1];

    float4 acc = make_float4(0.f, 0.f, 0.f, 0.f);
    float aS = 0.f, cg = 0.f;
    if (e > s) {
        float m = -1e30f;
        for (int p = s + lane; p < e; p += 32) m = fmaxf(m, g_araw[p]);
#pragma unroll
        for (int o = 16; o; o >>= 1)
            m = fmaxf(m, __shfl_xor_sync(0xffffffffu, m, o));
        float den = 0.f;
        for (int p = s + lane; p < e; p += 32) den += __expf(g_araw[p] - m);
#pragma unroll
        for (int o = 16; o; o >>= 1) den += __shfl_xor_sync(0xffffffffu, den, o);
        float invd = 1.f / den;

        int c3 = lane / 3;
        for (int p = s; p < e; p++) {
            float a = __expf(g_araw[p] - m) * invd;
            int c = g_cols[p];
            float4 hv = *(const float4*)&g_hv[(size_t)c * H + lane * 4];
            acc.x += a * hv.x;
            acc.y += a * hv.y;
            acc.z += a * hv.z;
            acc.w += a * hv.w;
            if (lane < 6) aS += a * g_rads[(size_t)p * 6 + lane];
            if (lane < 9)
                cg += g_cds[(size_t)p * 9 + lane] * (a * g_cvs[(size_t)p * 3 + c3]);
            if (lane == 0) alpha_out[g_perm[p]] = a;
        }
#pragma unroll
        for (int u = 0; u < 6; u++) {
            float asu = __shfl_sync(0xffffffffu, aS, u);
            acc.x += asu * wvr6_s[u * H + lane * 4 + 0];
            acc.y += asu * wvr6_s[u * H + lane * 4 + 1];
            acc.z += asu * wvr6_s[u * H + lane * 4 + 2];
            acc.w += asu * wvr6_s[u * H + lane * 4 + 3];
        }
    }
    float4 hh = *(const float4*)&h[(size_t)r * H + lane * 4];
    float4 o4 = make_float4(hh.x + acc.x, hh.y + acc.y, hh.z + acc.z, hh.w + acc.w);
    *(float4*)&out[(size_t)r * H + lane * 4] = o4;
    if (lane < 9) {
        float cgc = fminf(fmaxf(cg, -10.f), 10.f);
        out[(size_t)N * H + (size_t)r * 9 + lane] = coord[(size_t)r * 9 + lane] + cgc;
    }
}

// ---------------- launch -------------------------------------------------------
extern "C" void kernel_launch(void* const* d_in, const int* in_sizes, int n_in,
                              void* d_out, int out_size) {
    const float* h = (const float*)d_in[0];
    const float* coord = (const float*)d_in[1];
    const int* row = (const int*)d_in[2];
    const int* col = (const int*)d_in[3];
    const float* Wq = (const float*)d_in[4];
    const float* bq = (const float*)d_in[5];
    const float* Wkv = (const float*)d_in[6];
    const float* bkv = (const float*)d_in[7];
    const float* Wc1 = (const float*)d_in[8];
    const float* Wc2 = (const float*)d_in[9];
    int N = in_sizes[0] / H;
    int E = in_sizes[2];
    float* out = (float*)d_out;
    float* alpha_out = out + (size_t)N * H + (size_t)N * 9;

    size_t smem_z = (size_t)2 * 128 * BSTRIDE * sizeof(unsigned short);
    size_t smem_q = (size_t)4 * 128 * BSTRIDE * sizeof(unsigned short);
    cudaFuncSetAttribute((const void*)zgemm_kernel,
                         cudaFuncAttributeMaxDynamicSharedMemorySize, (int)smem_z);
    cudaFuncSetAttribute((const void*)qkv_gemm,
                         cudaFuncAttributeMaxDynamicSharedMemorySize, (int)smem_q);

    // CSR build
    zero_kernel<<<(N + 255) / 256, 256>>>(N);
    hist_kernel<<<(E + 255) / 256, 256>>>(row, E);
    scan_kernel<<<1, 1024>>>(N);
    scatter_kernel<<<(E + 255) / 256, 256>>>(row, col, E);

    // weight folds
    fold1_kernel<<<(H * H + 255) / 256, 256>>>(Wkv, bkv);
    fold2_kernel<<<(135 * ZDIM + 255) / 256, 256>>>(Wc1);
    fold3_kernel<<<(3 * 128 * 64 + 255) / 256, 256>>>(Wq);
    fold4_kernel<<<(ZDIM * 64 + 255) / 256, 256>>>();

    // node GEMMs (tensor cores)
    dim3 gq((N + 127) / 128, 3);
    qkv_gemm<<<gq, 256, smem_q>>>(h, bq, N);
    dim3 gz((N + 127) / 128, 4);
    zgemm_kernel<<<gz, 256, smem_z>>>(h, N);

    p_kernel<<<(N * 32 + 255) / 256, 256>>>(N);
    edge_kernel<<<((E + 7) / 8 * 32 + 255) / 256, 256>>>(Wc2, coord, E);
    row_kernel<<<(N + 7) / 8, 256>>>(h, coord, out, alpha_out, N);
}

// round 14
// speedup vs baseline: 1.1021x; 1.1021x over previous
#include <cuda_runtime.h>
#include <cuda_bf16.h>
#include <stdint.h>
#include <math.h>

#define H 128
#define KVDIM 256
#define ZDIM 512
#define NMAX 50000
#define EMAX 500000
#define BSTRIDE 136

// ---------------- scratch ------------------------------------------------------
__device__ float    g_hq[NMAX * H];
__device__ float    g_hk[NMAX * H];
__device__ float    g_hv[NMAX * H];
__device__ unsigned g_Zb[NMAX * (ZDIM / 2)];   // Z as packed bf16x2
__device__ float    g_P[NMAX * 6];
// CSR
__device__ int      g_cnt[NMAX];
__device__ int      g_off[NMAX + 1];
__device__ int      g_cur[NMAX];
__device__ int      g_perm[EMAX];
__device__ int      g_rows[EMAX];
__device__ int      g_cols[EMAX];
// sorted per-edge data
__device__ float    g_cds[EMAX * 9];
__device__ float    g_rads[EMAX * 6];
__device__ float    g_araw[EMAX];
__device__ float    g_cvs[EMAX * 3];
// folded weights
__device__ float    g_wkh[H * H];
__device__ float    g_wvh[H * H];
__device__ float    g_wkr6[6 * H];
__device__ float    g_wvr6[6 * H];
__device__ float    g_bk[H];
__device__ float    g_bv[H];
__device__ float    g_whz[H * ZDIM];
__device__ float    g_wvc16[6 * ZDIM];
__device__ float    g_bz[ZDIM];
// pre-transposed hi/lo bf16 weights for qkv tensor GEMM: [t][n][k] packed bf16x2
__device__ unsigned g_BhT[3 * 128 * 64];
__device__ unsigned g_BlT[3 * 128 * 64];
// pre-transposed bf16 whz for zgemm: [n][k] packed bf16x2
__device__ unsigned g_whzTb[ZDIM * 64];

// ---------------- helpers ------------------------------------------------------
__device__ __forceinline__ float silu_f(float x) {
    float t;
    asm("tanh.approx.f32 %0, %1;" : "=f"(t) : "f"(0.5f * x));
    return 0.5f * x * (1.f + t);
}
__device__ __forceinline__ unsigned bf16x2_of(float x0, float x1) {
    unsigned r;
    asm("cvt.rn.bf16x2.f32 %0, %1, %2;" : "=r"(r) : "f"(x1), "f"(x0));
    return r;
}
__device__ __forceinline__ void mma_bf16(float c[4], uint32_t a0, uint32_t a1,
                                         uint32_t a2, uint32_t a3, uint32_t b0,
                                         uint32_t b1) {
    asm volatile(
        "mma.sync.aligned.m16n8k16.row.col.f32.bf16.bf16.f32 "
        "{%0,%1,%2,%3}, {%4,%5,%6,%7}, {%8,%9}, {%0,%1,%2,%3};"
        : "+f"(c[0]), "+f"(c[1]), "+f"(c[2]), "+f"(c[3])
        : "r"(a0), "r"(a1), "r"(a2), "r"(a3), "r"(b0), "r"(b1));
}
__device__ __forceinline__ int sym_a(int u) { return (u < 3) ? 0 : ((u < 5) ? 1 : 2); }
__device__ __forceinline__ int sym_b(int u) { return (u < 3) ? u : ((u < 5) ? (u - 2) : 2); }

// ---------------- CSR build ----------------------------------------------------
__global__ void zero_kernel(int N) {
    int i = blockIdx.x * blockDim.x + threadIdx.x;
    if (i < N) g_cnt[i] = 0;
}
__global__ void hist_kernel(const int* __restrict__ row, int E) {
    int e = blockIdx.x * blockDim.x + threadIdx.x;
    if (e < E) atomicAdd(&g_cnt[row[e]], 1);
}
__global__ void scan_kernel(int N) {
    __shared__ int part[1024];
    int tid = threadIdx.x;
    int chunk = (N + 1023) / 1024;
    int s = tid * chunk;
    int e = min(s + chunk, N);
    int sum = 0;
    for (int i = s; i < e; i++) sum += g_cnt[i];
    part[tid] = sum;
    __syncthreads();
    for (int off = 1; off < 1024; off *= 2) {
        int v = (tid >= off) ? part[tid - off] : 0;
        __syncthreads();
        part[tid] += v;
        __syncthreads();
    }
    int run = tid ? part[tid - 1] : 0;
    for (int i = s; i < e; i++) {
        g_off[i] = run;
        g_cur[i] = run;
        run += g_cnt[i];
    }
    if (tid == 1023) g_off[N] = part[1023];
}
__global__ void scatter_kernel(const int* __restrict__ row,
                               const int* __restrict__ col, int E) {
    int e = blockIdx.x * blockDim.x + threadIdx.x;
    if (e >= E) return;
    int r = row[e];
    int pos = atomicAdd(&g_cur[r], 1);
    g_perm[pos] = e;
    g_rows[pos] = r;
    g_cols[pos] = col[e];
}

// ---------------- weight folds -------------------------------------------------
__global__ void fold1_kernel(const float* __restrict__ Wkv,
                             const float* __restrict__ bkv) {
    int idx = blockIdx.x * blockDim.x + threadIdx.x;
    if (idx < H * H) {
        int t = idx >> 7, m = idx & 127;
        g_wkh[idx] = Wkv[(9 + t) * KVDIM + 2 * m];
        g_wvh[idx] = Wkv[(9 + t) * KVDIM + 2 * m + 1];
    }
    if (idx < 6 * H) {
        int u = idx >> 7, m = idx & 127;
        int a = sym_a(u), b = sym_b(u);
        int i1 = a * 3 + b, i2 = b * 3 + a;
        float k = Wkv[i1 * KVDIM + 2 * m];
        float v = Wkv[i1 * KVDIM + 2 * m + 1];
        if (i1 != i2) {
            k += Wkv[i2 * KVDIM + 2 * m];
            v += Wkv[i2 * KVDIM + 2 * m + 1];
        }
        g_wkr6[idx] = k;
        g_wvr6[idx] = v;
    }
    if (idx < H) {
        g_bk[idx] = bkv[2 * idx];
        g_bv[idx] = bkv[2 * idx + 1];
    }
}
__global__ void fold2_kernel(const float* __restrict__ Wc1) {
    int idx = blockIdx.x * blockDim.x + threadIdx.x;
    if (idx >= 135 * ZDIM) return;
    int t = idx / ZDIM, j = idx % ZDIM;
    const float* arow;
    if (t < 128) arow = &g_wvh[t * H];
    else if (t < 134) arow = &g_wvr6[(t - 128) * H];
    else arow = g_bv;
    float acc = 0.f;
#pragma unroll 8
    for (int m = 0; m < H; m++) acc += arow[m] * Wc1[(size_t)m * ZDIM + j];
    if (t < 128) g_whz[t * ZDIM + j] = acc;
    else if (t < 134) g_wvc16[(t - 128) * ZDIM + j] = acc;
    else g_bz[j] = acc;
}
// fold3: transpose + hi/lo-split Wq / wkh / wvh (needs fold1)
__global__ void fold3_kernel(const float* __restrict__ Wq) {
    int idx = blockIdx.x * blockDim.x + threadIdx.x;
    if (idx >= 3 * 128 * 64) return;
    int t = idx / 8192, rem = idx % 8192;
    int n = rem >> 6, k2 = rem & 63;
    const float* B = (t == 0) ? Wq : ((t == 1) ? g_wkh : g_wvh);
    float v0 = B[(size_t)(2 * k2) * H + n];
    float v1 = B[(size_t)(2 * k2 + 1) * H + n];
    unsigned hi = bf16x2_of(v0, v1);
    float h0 = __uint_as_float(hi << 16);
    float h1 = __uint_as_float(hi & 0xffff0000u);
    g_BhT[idx] = hi;
    g_BlT[idx] = bf16x2_of(v0 - h0, v1 - h1);
}
// fold4: transpose + bf16-pack whz for zgemm (needs fold2)
__global__ void fold4_kernel() {
    int idx = blockIdx.x * blockDim.x + threadIdx.x;
    if (idx >= ZDIM * 64) return;
    int n = idx >> 6, k2 = idx & 63;
    float v0 = g_whz[(size_t)(2 * k2) * ZDIM + n];
    float v1 = g_whz[(size_t)(2 * k2 + 1) * ZDIM + n];
    g_whzTb[idx] = bf16x2_of(v0, v1);
}

// ---------------- split-bf16 tensor GEMM for hq/hk/hv -------------------------
__global__ __launch_bounds__(256) void qkv_gemm(const float* __restrict__ h,
                                                const float* __restrict__ bq,
                                                int N) {
    extern __shared__ unsigned short qsm[];
    unsigned short* Ah = qsm;                    // [128][BSTRIDE]
    unsigned short* Al = Ah + 128 * BSTRIDE;
    unsigned short* Bh = Al + 128 * BSTRIDE;     // [n][k]
    unsigned short* Bl = Bh + 128 * BSTRIDE;

    int tid = threadIdx.x;
    int wid = tid >> 5, lane = tid & 31;
    int gid = lane >> 2, tig = lane & 3;
    int n0 = blockIdx.x * 128;
    int y = blockIdx.y;

    const float* bias;
    float* C;
    if (y == 0)      { bias = bq;   C = g_hq; }
    else if (y == 1) { bias = g_bk; C = g_hk; }
    else             { bias = g_bv; C = g_hv; }

    for (int idx = tid; idx < 128 * 64; idx += 256) {
        int row = idx >> 6, j = idx & 63;
        float2 f = make_float2(0.f, 0.f);
        if (n0 + row < N) f = *(const float2*)&h[(size_t)(n0 + row) * H + 2 * j];
        unsigned hi2 = bf16x2_of(f.x, f.y);
        float hx = __uint_as_float(hi2 << 16);
        float hy = __uint_as_float(hi2 & 0xffff0000u);
        unsigned lo2 = bf16x2_of(f.x - hx, f.y - hy);
        *(unsigned*)&Ah[row * BSTRIDE + 2 * j] = hi2;
        *(unsigned*)&Al[row * BSTRIDE + 2 * j] = lo2;
    }
    {
        const unsigned* bh = &g_BhT[y * 8192];
        const unsigned* bl = &g_BlT[y * 8192];
        for (int idx = tid; idx < 128 * 64; idx += 256) {
            int n = idx >> 6, k2 = idx & 63;
            *(unsigned*)&Bh[n * BSTRIDE + 2 * k2] = bh[idx];
            *(unsigned*)&Bl[n * BSTRIDE + 2 * k2] = bl[idx];
        }
    }
    __syncthreads();

    int wm = (wid & 3) * 32;
    int wn = (wid >> 2) * 64;

    float c[2][8][4];
#pragma unroll
    for (int mt = 0; mt < 2; mt++)
#pragma unroll
        for (int ntl = 0; ntl < 8; ntl++)
#pragma unroll
            for (int q = 0; q < 4; q++) c[mt][ntl][q] = 0.f;

#pragma unroll
    for (int k0 = 0; k0 < 128; k0 += 16) {
        uint32_t ah[2][4], al[2][4];
#pragma unroll
        for (int mt = 0; mt < 2; mt++) {
            int row = wm + mt * 16;
            int o0 = (row + gid) * BSTRIDE + k0 + 2 * tig;
            int o1 = (row + gid + 8) * BSTRIDE + k0 + 2 * tig;
            ah[mt][0] = *(const unsigned*)&Ah[o0];
            ah[mt][1] = *(const unsigned*)&Ah[o1];
            ah[mt][2] = *(const unsigned*)&Ah[o0 + 8];
            ah[mt][3] = *(const unsigned*)&Ah[o1 + 8];
            al[mt][0] = *(const unsigned*)&Al[o0];
            al[mt][1] = *(const unsigned*)&Al[o1];
            al[mt][2] = *(const unsigned*)&Al[o0 + 8];
            al[mt][3] = *(const unsigned*)&Al[o1 + 8];
        }
#pragma unroll
        for (int ntl = 0; ntl < 8; ntl++) {
            int col = wn + ntl * 8 + gid;
            int ob = col * BSTRIDE + k0 + 2 * tig;
            uint32_t bh0 = *(const unsigned*)&Bh[ob];
            uint32_t bh1 = *(const unsigned*)&Bh[ob + 8];
            uint32_t bl0 = *(const unsigned*)&Bl[ob];
            uint32_t bl1 = *(const unsigned*)&Bl[ob + 8];
#pragma unroll
            for (int mt = 0; mt < 2; mt++) {
                mma_bf16(c[mt][ntl], ah[mt][0], ah[mt][1], ah[mt][2], ah[mt][3],
                         bh0, bh1);
                mma_bf16(c[mt][ntl], ah[mt][0], ah[mt][1], ah[mt][2], ah[mt][3],
                         bl0, bl1);
                mma_bf16(c[mt][ntl], al[mt][0], al[mt][1], al[mt][2], al[mt][3],
                         bh0, bh1);
            }
        }
    }

#pragma unroll
    for (int mt = 0; mt < 2; mt++) {
        int r0 = n0 + wm + mt * 16 + gid;
#pragma unroll
        for (int ntl = 0; ntl < 8; ntl++) {
            int gcol = wn + ntl * 8 + 2 * tig;
            float b0 = bias[gcol], b1 = bias[gcol + 1];
            if (r0 < N)
                *(float2*)&C[(size_t)r0 * H + gcol] =
                    make_float2(c[mt][ntl][0] + b0, c[mt][ntl][1] + b1);
            if (r0 + 8 < N)
                *(float2*)&C[(size_t)(r0 + 8) * H + gcol] =
                    make_float2(c[mt][ntl][2] + b0, c[mt][ntl][3] + b1);
        }
    }
}

// ---------------- mma.sync bf16 Z GEMM: Zb = bf16(h @ whz + bz) ---------------
__global__ __launch_bounds__(256) void zgemm_kernel(const float* __restrict__ h,
                                                    int N) {
    extern __shared__ unsigned short zsm[];
    unsigned short* As = zsm;                  // [128][BSTRIDE]
    unsigned short* Bs = zsm + 128 * BSTRIDE;  // [n][k]

    int tid = threadIdx.x;
    int wid = tid >> 5, lane = tid & 31;
    int gid = lane >> 2, tig = lane & 3;
    int n0 = blockIdx.x * 128;
    int nt = blockIdx.y * 128;

    for (int idx = tid; idx < 128 * 64; idx += 256) {
        int row = idx >> 6, j = idx & 63;
        float2 f = make_float2(0.f, 0.f);
        if (n0 + row < N) f = *(const float2*)&h[(size_t)(n0 + row) * H + 2 * j];
        *(unsigned*)&As[row * BSTRIDE + 2 * j] = bf16x2_of(f.x, f.y);
    }
    {
        const unsigned* bsrc = &g_whzTb[(size_t)nt * 64];
        for (int idx = tid; idx < 128 * 64; idx += 256) {
            int n = idx >> 6, k2 = idx & 63;
            *(unsigned*)&Bs[n * BSTRIDE + 2 * k2] = bsrc[idx];
        }
    }
    __syncthreads();

    int wm = (wid & 3) * 32;
    int wn = (wid >> 2) * 64;

    float c[2][8][4];
#pragma unroll
    for (int mt = 0; mt < 2; mt++)
#pragma unroll
        for (int ntl = 0; ntl < 8; ntl++)
#pragma unroll
            for (int q = 0; q < 4; q++) c[mt][ntl][q] = 0.f;

#pragma unroll
    for (int k0 = 0; k0 < 128; k0 += 16) {
        uint32_t a[2][4];
#pragma unroll
        for (int mt = 0; mt < 2; mt++) {
            int row = wm + mt * 16;
            a[mt][0] = *(const unsigned*)&As[(row + gid) * BSTRIDE + k0 + 2 * tig];
            a[mt][1] = *(const unsigned*)&As[(row + gid + 8) * BSTRIDE + k0 + 2 * tig];
            a[mt][2] = *(const unsigned*)&As[(row + gid) * BSTRIDE + k0 + 2 * tig + 8];
            a[mt][3] = *(const unsigned*)&As[(row + gid + 8) * BSTRIDE + k0 + 2 * tig + 8];
        }
        uint32_t b[8][2];
#pragma unroll
        for (int ntl = 0; ntl < 8; ntl++) {
            int col = wn + ntl * 8 + gid;
            b[ntl][0] = *(const unsigned*)&Bs[col * BSTRIDE + k0 + 2 * tig];
            b[ntl][1] = *(const unsigned*)&Bs[col * BSTRIDE + k0 + 2 * tig + 8];
        }
#pragma unroll
        for (int mt = 0; mt < 2; mt++)
#pragma unroll
            for (int ntl = 0; ntl < 8; ntl++)
                mma_bf16(c[mt][ntl], a[mt][0], a[mt][1], a[mt][2], a[mt][3],
                         b[ntl][0], b[ntl][1]);
    }

#pragma unroll
    for (int mt = 0; mt < 2; mt++) {
        int r0 = n0 + wm + mt * 16 + gid;
#pragma unroll
        for (int ntl = 0; ntl < 8; ntl++) {
            int gcol = nt + wn + ntl * 8 + 2 * tig;
            float bz0 = g_bz[gcol], bz1 = g_bz[gcol + 1];
            if (r0 < N)
                g_Zb[(size_t)r0 * (ZDIM / 2) + (gcol >> 1)] =
                    bf16x2_of(c[mt][ntl][0] + bz0, c[mt][ntl][1] + bz1);
            if (r0 + 8 < N)
                g_Zb[(size_t)(r0 + 8) * (ZDIM / 2) + (gcol >> 1)] =
                    bf16x2_of(c[mt][ntl][2] + bz0, c[mt][ntl][3] + bz1);
        }
    }
}

// ---------------- P6: warp per node -------------------------------------------
__global__ void p_kernel(int N) {
    int r = (int)((blockIdx.x * blockDim.x + threadIdx.x) >> 5);
    int lane = threadIdx.x & 31;
    if (r >= N) return;
    float4 q = *(const float4*)&g_hq[(size_t)r * H + lane * 4];
#pragma unroll
    for (int u = 0; u < 6; u++) {
        float4 w = *(const float4*)&g_wkr6[u * H + lane * 4];
        float s = q.x * w.x + q.y * w.y + q.z * w.z + q.w * w.w;
#pragma unroll
        for (int o = 16; o; o >>= 1) s += __shfl_xor_sync(0xffffffffu, s, o);
        if (lane == 0) g_P[r * 6 + u] = s;
    }
}

// ---------------- edge prep (sorted order, warp per edge) ---------------------
__global__ void edge_prep_kernel(const float* __restrict__ coord, int E) {
    int p = (int)((blockIdx.x * blockDim.x + threadIdx.x) >> 5);
    int lane = threadIdx.x & 31;
    if (p >= E) return;
    int r = g_rows[p], c = g_cols[p];

    float cdv = 0.f;
    if (lane < 9) cdv = coord[(size_t)r * 9 + lane] - coord[(size_t)c * 9 + lane];
    if (lane < 9) g_cds[(size_t)p * 9 + lane] = cdv;
    float cd[9];
#pragma unroll
    for (int i = 0; i < 9; i++) cd[i] = __shfl_sync(0xffffffffu, cdv, i);

    float radv = 0.f;
    if (lane < 6) {
        int a = sym_a(lane), b = sym_b(lane);
        radv = cd[a * 3] * cd[b * 3] + cd[a * 3 + 1] * cd[b * 3 + 1] +
               cd[a * 3 + 2] * cd[b * 3 + 2];
        g_rads[(size_t)p * 6 + lane] = radv;
    }

    float4 q = *(const float4*)&g_hq[(size_t)r * H + lane * 4];
    float4 k = *(const float4*)&g_hk[(size_t)c * H + lane * 4];
    float ap = q.x * k.x + q.y * k.y + q.z * k.z + q.w * k.w;
    if (lane < 6) ap += radv * g_P[r * 6 + lane];
#pragma unroll
    for (int o = 16; o; o >>= 1) ap += __shfl_xor_sync(0xffffffffu, ap, o);
    if (lane == 0) g_araw[p] = ap;
}

// ---------------- cv kernel: warp per 8 edges (6 folded rad terms) ------------
__global__ __launch_bounds__(256) void cv_kernel(const float* __restrict__ Wc2,
                                                 int E) {
    int lane = threadIdx.x & 31;
    int wg = (int)((blockIdx.x * blockDim.x + threadIdx.x) >> 5);
    int e0 = wg * 8;
    if (e0 >= E) return;

    int cols[8];
    float rr[8];
#pragma unroll
    for (int g = 0; g < 8; g++) {
        int e = e0 + g;
        cols[g] = (e < E) ? g_cols[e] : 0;
        rr[g] = (lane < 6 && e < E) ? g_rads[(size_t)e * 6 + lane] : 0.f;
    }
    float pacc[8][3];
#pragma unroll
    for (int g = 0; g < 8; g++) pacc[g][0] = pacc[g][1] = pacc[g][2] = 0.f;

    for (int jc = 0; jc < 4; jc++) {
        int j0 = jc * 128 + lane * 4;
        float wv[6][4];
#pragma unroll
        for (int u = 0; u < 6; u++) {
            float4 f = *(const float4*)&g_wvc16[u * ZDIM + j0];
            wv[u][0] = f.x; wv[u][1] = f.y; wv[u][2] = f.z; wv[u][3] = f.w;
        }
        float w2[4][3];
#pragma unroll
        for (int jj = 0; jj < 4; jj++)
#pragma unroll
            for (int d = 0; d < 3; d++) w2[jj][d] = Wc2[(j0 + jj) * 3 + d];

#pragma unroll
        for (int g = 0; g < 8; g++) {
            uint2 z = *(const uint2*)&g_Zb[(size_t)cols[g] * (ZDIM / 2) + (j0 >> 1)];
            float x0 = __uint_as_float(z.x << 16);
            float x1 = __uint_as_float(z.x & 0xffff0000u);
            float x2 = __uint_as_float(z.y << 16);
            float x3 = __uint_as_float(z.y & 0xffff0000u);
#pragma unroll
            for (int u = 0; u < 6; u++) {
                float ri = __shfl_sync(0xffffffffu, rr[g], u);
                x0 += ri * wv[u][0];
                x1 += ri * wv[u][1];
                x2 += ri * wv[u][2];
                x3 += ri * wv[u][3];
            }
            float u0 = silu_f(x0), u1 = silu_f(x1), u2 = silu_f(x2), u3 = silu_f(x3);
#pragma unroll
            for (int d = 0; d < 3; d++)
                pacc[g][d] += u0 * w2[0][d] + u1 * w2[1][d] + u2 * w2[2][d] +
                              u3 * w2[3][d];
        }
    }
#pragma unroll
    for (int g = 0; g < 8; g++) {
        float p0 = pacc[g][0], p1 = pacc[g][1], p2 = pacc[g][2];
#pragma unroll
        for (int o = 16; o; o >>= 1) {
            p0 += __shfl_xor_sync(0xffffffffu, p0, o);
            p1 += __shfl_xor_sync(0xffffffffu, p1, o);
            p2 += __shfl_xor_sync(0xffffffffu, p2, o);
        }
        if (lane == 0 && e0 + g < E) {
            g_cvs[(size_t)(e0 + g) * 3 + 0] = p0;
            g_cvs[(size_t)(e0 + g) * 3 + 1] = p1;
            g_cvs[(size_t)(e0 + g) * 3 + 2] = p2;
        }
    }
}

// ---------------- row kernel: softmax + agg + finalize ------------------------
__global__ __launch_bounds__(256) void row_kernel(
    const float* __restrict__ h, const float* __restrict__ coord,
    float* __restrict__ out, float* __restrict__ alpha_out, int N) {
    __shared__ float wvr6_s[6 * H];
    int tid = threadIdx.x, lane = tid & 31, w = tid >> 5;
    for (int i = tid; i < 6 * H; i += 256) wvr6_s[i] = g_wvr6[i];
    __syncthreads();
    int r = blockIdx.x * 8 + w;
    if (r >= N) return;
    int s = g_off[r], e = g_off[r + 1];

    float4 acc = make_float4(0.f, 0.f, 0.f, 0.f);
    float aS = 0.f, cg = 0.f;
    if (e > s) {
        float m = -1e30f;
        for (int p = s + lane; p < e; p += 32) m = fmaxf(m, g_araw[p]);
#pragma unroll
        for (int o = 16; o; o >>= 1)
            m = fmaxf(m, __shfl_xor_sync(0xffffffffu, m, o));
        float den = 0.f;
        for (int p = s + lane; p < e; p += 32) den += __expf(g_araw[p] - m);
#pragma unroll
        for (int o = 16; o; o >>= 1) den += __shfl_xor_sync(0xffffffffu, den, o);
        float invd = 1.f / den;

        int c3 = lane / 3;
        for (int p = s; p < e; p++) {
            float a = __expf(g_araw[p] - m) * invd;
            int c = g_cols[p];
            float4 hv = *(const float4*)&g_hv[(size_t)c * H + lane * 4];
            acc.x += a * hv.x;
            acc.y += a * hv.y;
            acc.z += a * hv.z;
            acc.w += a * hv.w;
            if (lane < 6) aS += a * g_rads[(size_t)p * 6 + lane];
            if (lane < 9)
                cg += g_cds[(size_t)p * 9 + lane] * (a * g_cvs[(size_t)p * 3 + c3]);
            if (lane == 0) alpha_out[g_perm[p]] = a;
        }
#pragma unroll
        for (int u = 0; u < 6; u++) {
            float asu = __shfl_sync(0xffffffffu, aS, u);
            acc.x += asu * wvr6_s[u * H + lane * 4 + 0];
            acc.y += asu * wvr6_s[u * H + lane * 4 + 1];
            acc.z += asu * wvr6_s[u * H + lane * 4 + 2];
            acc.w += asu * wvr6_s[u * H + lane * 4 + 3];
        }
    }
    float4 hh = *(const float4*)&h[(size_t)r * H + lane * 4];
    float4 o4 = make_float4(hh.x + acc.x, hh.y + acc.y, hh.z + acc.z, hh.w + acc.w);
    *(float4*)&out[(size_t)r * H + lane * 4] = o4;
    if (lane < 9) {
        float cgc = fminf(fmaxf(cg, -10.f), 10.f);
        out[(size_t)N * H + (size_t)r * 9 + lane] = coord[(size_t)r * 9 + lane] + cgc;
    }
}

// ---------------- launch -------------------------------------------------------
extern "C" void kernel_launch(void* const* d_in, const int* in_sizes, int n_in,
                              void* d_out, int out_size) {
    const float* h = (const float*)d_in[0];
    const float* coord = (const float*)d_in[1];
    const int* row = (const int*)d_in[2];
    const int* col = (const int*)d_in[3];
    const float* Wq = (const float*)d_in[4];
    const float* bq = (const float*)d_in[5];
    const float* Wkv = (const float*)d_in[6];
    const float* bkv = (const float*)d_in[7];
    const float* Wc1 = (const float*)d_in[8];
    const float* Wc2 = (const float*)d_in[9];
    int N = in_sizes[0] / H;
    int E = in_sizes[2];
    float* out = (float*)d_out;
    float* alpha_out = out + (size_t)N * H + (size_t)N * 9;

    size_t smem_z = (size_t)2 * 128 * BSTRIDE * sizeof(unsigned short);
    size_t smem_q = (size_t)4 * 128 * BSTRIDE * sizeof(unsigned short);
    cudaFuncSetAttribute((const void*)zgemm_kernel,
                         cudaFuncAttributeMaxDynamicSharedMemorySize, (int)smem_z);
    cudaFuncSetAttribute((const void*)qkv_gemm,
                         cudaFuncAttributeMaxDynamicSharedMemorySize, (int)smem_q);

    // CSR build
    zero_kernel<<<(N + 255) / 256, 256>>>(N);
    hist_kernel<<<(E + 255) / 256, 256>>>(row, E);
    scan_kernel<<<1, 1024>>>(N);
    scatter_kernel<<<(E + 255) / 256, 256>>>(row, col, E);

    // weight folds
    fold1_kernel<<<(H * H + 255) / 256, 256>>>(Wkv, bkv);
    fold2_kernel<<<(135 * ZDIM + 255) / 256, 256>>>(Wc1);
    fold3_kernel<<<(3 * 128 * 64 + 255) / 256, 256>>>(Wq);
    fold4_kernel<<<(ZDIM * 64 + 255) / 256, 256>>>();

    // node GEMMs (tensor cores)
    dim3 gq((N + 127) / 128, 3);
    qkv_gemm<<<gq, 256, smem_q>>>(h, bq, N);
    dim3 gz((N + 127) / 128, 4);
    zgemm_kernel<<<gz, 256, smem_z>>>(h, N);

    p_kernel<<<(N * 32 + 255) / 256, 256>>>(N);
    edge_prep_kernel<<<(E * 32 + 255) / 256, 256>>>(coord, E);
    cv_kernel<<<((E + 7) / 8 * 32 + 255) / 256, 256>>>(Wc2, E);
    row_kernel<<<(N + 7) / 8, 256>>>(h, coord, out, alpha_out, N);
}

// round 15
// speedup vs baseline: 1.1683x; 1.0601x over previous
#include <cuda_runtime.h>
#include <cuda_bf16.h>
#include <stdint.h>
#include <math.h>

#define H 128
#define KVDIM 256
#define ZDIM 512
#define NMAX 50000
#define EMAX 500000
#define BSTRIDE 136

// ---------------- scratch ------------------------------------------------------
__device__ float    g_hq[NMAX * H];
__device__ float    g_hk[NMAX * H];
__device__ float    g_hv[NMAX * H];
__device__ unsigned g_Zb[NMAX * (ZDIM / 2)];   // Z as packed bf16x2
__device__ float    g_P[NMAX * 6];
// CSR
__device__ int      g_cnt[NMAX];
__device__ int      g_off[NMAX + 1];
__device__ int      g_cur[NMAX];
__device__ int      g_perm[EMAX];
__device__ int      g_rows[EMAX];
__device__ int      g_cols[EMAX];
// sorted per-edge data
__device__ float    g_cds[EMAX * 9];
__device__ float    g_rads[EMAX * 6];
__device__ float    g_araw[EMAX];
__device__ float    g_cvs[EMAX * 3];
// folded weights
__device__ float    g_wkh[H * H];
__device__ float    g_wvh[H * H];
__device__ float    g_wkr6[6 * H];
__device__ float    g_wvr6[6 * H];
__device__ float    g_bk[H];
__device__ float    g_bv[H];
__device__ float    g_whz[H * ZDIM];
__device__ float    g_wvc16[6 * ZDIM];
__device__ float    g_bz[ZDIM];
// pre-transposed hi/lo bf16 weights for qkv tensor GEMM: [t][n][k] packed bf16x2
__device__ unsigned g_BhT[3 * 128 * 64];
__device__ unsigned g_BlT[3 * 128 * 64];
// pre-transposed bf16 whz for zgemm: [n][k] packed bf16x2
__device__ unsigned g_whzTb[ZDIM * 64];

// ---------------- helpers ------------------------------------------------------
__device__ __forceinline__ float silu_f(float x) {
    float t;
    asm("tanh.approx.f32 %0, %1;" : "=f"(t) : "f"(0.5f * x));
    return 0.5f * x * (1.f + t);
}
__device__ __forceinline__ unsigned bf16x2_of(float x0, float x1) {
    unsigned r;
    asm("cvt.rn.bf16x2.f32 %0, %1, %2;" : "=r"(r) : "f"(x1), "f"(x0));
    return r;
}
__device__ __forceinline__ void mma_bf16(float c[4], uint32_t a0, uint32_t a1,
                                         uint32_t a2, uint32_t a3, uint32_t b0,
                                         uint32_t b1) {
    asm volatile(
        "mma.sync.aligned.m16n8k16.row.col.f32.bf16.bf16.f32 "
        "{%0,%1,%2,%3}, {%4,%5,%6,%7}, {%8,%9}, {%0,%1,%2,%3};"
        : "+f"(c[0]), "+f"(c[1]), "+f"(c[2]), "+f"(c[3])
        : "r"(a0), "r"(a1), "r"(a2), "r"(a3), "r"(b0), "r"(b1));
}
__device__ __forceinline__ int sym_a(int u) { return (u < 3) ? 0 : ((u < 5) ? 1 : 2); }
__device__ __forceinline__ int sym_b(int u) { return (u < 3) ? u : ((u < 5) ? (u - 2) : 2); }

// ---------------- CSR build ----------------------------------------------------
__global__ void zero_kernel(int N) {
    int i = blockIdx.x * blockDim.x + threadIdx.x;
    if (i < N) g_cnt[i] = 0;
}
__global__ void hist_kernel(const int* __restrict__ row, int E) {
    int e = blockIdx.x * blockDim.x + threadIdx.x;
    if (e < E) atomicAdd(&g_cnt[row[e]], 1);
}
__global__ void scan_kernel(int N) {
    __shared__ int part[1024];
    int tid = threadIdx.x;
    int chunk = (N + 1023) / 1024;
    int s = tid * chunk;
    int e = min(s + chunk, N);
    int sum = 0;
    for (int i = s; i < e; i++) sum += g_cnt[i];
    part[tid] = sum;
    __syncthreads();
    for (int off = 1; off < 1024; off *= 2) {
        int v = (tid >= off) ? part[tid - off] : 0;
        __syncthreads();
        part[tid] += v;
        __syncthreads();
    }
    int run = tid ? part[tid - 1] : 0;
    for (int i = s; i < e; i++) {
        g_off[i] = run;
        g_cur[i] = run;
        run += g_cnt[i];
    }
    if (tid == 1023) g_off[N] = part[1023];
}
__global__ void scatter_kernel(const int* __restrict__ row,
                               const int* __restrict__ col, int E) {
    int e = blockIdx.x * blockDim.x + threadIdx.x;
    if (e >= E) return;
    int r = row[e];
    int pos = atomicAdd(&g_cur[r], 1);
    g_perm[pos] = e;
    g_rows[pos] = r;
    g_cols[pos] = col[e];
}

// ---------------- weight folds -------------------------------------------------
__global__ void fold1_kernel(const float* __restrict__ Wkv,
                             const float* __restrict__ bkv) {
    int idx = blockIdx.x * blockDim.x + threadIdx.x;
    if (idx < H * H) {
        int t = idx >> 7, m = idx & 127;
        g_wkh[idx] = Wkv[(9 + t) * KVDIM + 2 * m];
        g_wvh[idx] = Wkv[(9 + t) * KVDIM + 2 * m + 1];
    }
    if (idx < 6 * H) {
        int u = idx >> 7, m = idx & 127;
        int a = sym_a(u), b = sym_b(u);
        int i1 = a * 3 + b, i2 = b * 3 + a;
        float k = Wkv[i1 * KVDIM + 2 * m];
        float v = Wkv[i1 * KVDIM + 2 * m + 1];
        if (i1 != i2) {
            k += Wkv[i2 * KVDIM + 2 * m];
            v += Wkv[i2 * KVDIM + 2 * m + 1];
        }
        g_wkr6[idx] = k;
        g_wvr6[idx] = v;
    }
    if (idx < H) {
        g_bk[idx] = bkv[2 * idx];
        g_bv[idx] = bkv[2 * idx + 1];
    }
}
__global__ void fold2_kernel(const float* __restrict__ Wc1) {
    int idx = blockIdx.x * blockDim.x + threadIdx.x;
    if (idx >= 135 * ZDIM) return;
    int t = idx / ZDIM, j = idx % ZDIM;
    const float* arow;
    if (t < 128) arow = &g_wvh[t * H];
    else if (t < 134) arow = &g_wvr6[(t - 128) * H];
    else arow = g_bv;
    float acc = 0.f;
#pragma unroll 8
    for (int m = 0; m < H; m++) acc += arow[m] * Wc1[(size_t)m * ZDIM + j];
    if (t < 128) g_whz[t * ZDIM + j] = acc;
    else if (t < 134) g_wvc16[(t - 128) * ZDIM + j] = acc;
    else g_bz[j] = acc;
}
// fold3: transpose + hi/lo-split Wq / wkh / wvh (needs fold1)
__global__ void fold3_kernel(const float* __restrict__ Wq) {
    int idx = blockIdx.x * blockDim.x + threadIdx.x;
    if (idx >= 3 * 128 * 64) return;
    int t = idx / 8192, rem = idx % 8192;
    int n = rem >> 6, k2 = rem & 63;
    const float* B = (t == 0) ? Wq : ((t == 1) ? g_wkh : g_wvh);
    float v0 = B[(size_t)(2 * k2) * H + n];
    float v1 = B[(size_t)(2 * k2 + 1) * H + n];
    unsigned hi = bf16x2_of(v0, v1);
    float h0 = __uint_as_float(hi << 16);
    float h1 = __uint_as_float(hi & 0xffff0000u);
    g_BhT[idx] = hi;
    g_BlT[idx] = bf16x2_of(v0 - h0, v1 - h1);
}
// fold4: transpose + bf16-pack whz for zgemm (needs fold2)
__global__ void fold4_kernel() {
    int idx = blockIdx.x * blockDim.x + threadIdx.x;
    if (idx >= ZDIM * 64) return;
    int n = idx >> 6, k2 = idx & 63;
    float v0 = g_whz[(size_t)(2 * k2) * ZDIM + n];
    float v1 = g_whz[(size_t)(2 * k2 + 1) * ZDIM + n];
    g_whzTb[idx] = bf16x2_of(v0, v1);
}

// ---------------- split-bf16 tensor GEMM for hq/hk/hv -------------------------
__global__ __launch_bounds__(256) void qkv_gemm(const float* __restrict__ h,
                                                const float* __restrict__ bq,
                                                int N) {
    extern __shared__ unsigned short qsm[];
    unsigned short* Ah = qsm;                    // [128][BSTRIDE]
    unsigned short* Al = Ah + 128 * BSTRIDE;
    unsigned short* Bh = Al + 128 * BSTRIDE;     // [n][k]
    unsigned short* Bl = Bh + 128 * BSTRIDE;

    int tid = threadIdx.x;
    int wid = tid >> 5, lane = tid & 31;
    int gid = lane >> 2, tig = lane & 3;
    int n0 = blockIdx.x * 128;
    int y = blockIdx.y;

    const float* bias;
    float* C;
    if (y == 0)      { bias = bq;   C = g_hq; }
    else if (y == 1) { bias = g_bk; C = g_hk; }
    else             { bias = g_bv; C = g_hv; }

    for (int idx = tid; idx < 128 * 64; idx += 256) {
        int row = idx >> 6, j = idx & 63;
        float2 f = make_float2(0.f, 0.f);
        if (n0 + row < N) f = *(const float2*)&h[(size_t)(n0 + row) * H + 2 * j];
        unsigned hi2 = bf16x2_of(f.x, f.y);
        float hx = __uint_as_float(hi2 << 16);
        float hy = __uint_as_float(hi2 & 0xffff0000u);
        unsigned lo2 = bf16x2_of(f.x - hx, f.y - hy);
        *(unsigned*)&Ah[row * BSTRIDE + 2 * j] = hi2;
        *(unsigned*)&Al[row * BSTRIDE + 2 * j] = lo2;
    }
    {
        const unsigned* bh = &g_BhT[y * 8192];
        const unsigned* bl = &g_BlT[y * 8192];
        for (int idx = tid; idx < 128 * 64; idx += 256) {
            int n = idx >> 6, k2 = idx & 63;
            *(unsigned*)&Bh[n * BSTRIDE + 2 * k2] = bh[idx];
            *(unsigned*)&Bl[n * BSTRIDE + 2 * k2] = bl[idx];
        }
    }
    __syncthreads();

    int wm = (wid & 3) * 32;
    int wn = (wid >> 2) * 64;

    float c[2][8][4];
#pragma unroll
    for (int mt = 0; mt < 2; mt++)
#pragma unroll
        for (int ntl = 0; ntl < 8; ntl++)
#pragma unroll
            for (int q = 0; q < 4; q++) c[mt][ntl][q] = 0.f;

#pragma unroll
    for (int k0 = 0; k0 < 128; k0 += 16) {
        uint32_t ah[2][4], al[2][4];
#pragma unroll
        for (int mt = 0; mt < 2; mt++) {
            int row = wm + mt * 16;
            int o0 = (row + gid) * BSTRIDE + k0 + 2 * tig;
            int o1 = (row + gid + 8) * BSTRIDE + k0 + 2 * tig;
            ah[mt][0] = *(const unsigned*)&Ah[o0];
            ah[mt][1] = *(const unsigned*)&Ah[o1];
            ah[mt][2] = *(const unsigned*)&Ah[o0 + 8];
            ah[mt][3] = *(const unsigned*)&Ah[o1 + 8];
            al[mt][0] = *(const unsigned*)&Al[o0];
            al[mt][1] = *(const unsigned*)&Al[o1];
            al[mt][2] = *(const unsigned*)&Al[o0 + 8];
            al[mt][3] = *(const unsigned*)&Al[o1 + 8];
        }
#pragma unroll
        for (int ntl = 0; ntl < 8; ntl++) {
            int col = wn + ntl * 8 + gid;
            int ob = col * BSTRIDE + k0 + 2 * tig;
            uint32_t bh0 = *(const unsigned*)&Bh[ob];
            uint32_t bh1 = *(const unsigned*)&Bh[ob + 8];
            uint32_t bl0 = *(const unsigned*)&Bl[ob];
            uint32_t bl1 = *(const unsigned*)&Bl[ob + 8];
#pragma unroll
            for (int mt = 0; mt < 2; mt++) {
                mma_bf16(c[mt][ntl], ah[mt][0], ah[mt][1], ah[mt][2], ah[mt][3],
                         bh0, bh1);
                mma_bf16(c[mt][ntl], ah[mt][0], ah[mt][1], ah[mt][2], ah[mt][3],
                         bl0, bl1);
                mma_bf16(c[mt][ntl], al[mt][0], al[mt][1], al[mt][2], al[mt][3],
                         bh0, bh1);
            }
        }
    }

#pragma unroll
    for (int mt = 0; mt < 2; mt++) {
        int r0 = n0 + wm + mt * 16 + gid;
#pragma unroll
        for (int ntl = 0; ntl < 8; ntl++) {
            int gcol = wn + ntl * 8 + 2 * tig;
            float b0 = bias[gcol], b1 = bias[gcol + 1];
            if (r0 < N)
                *(float2*)&C[(size_t)r0 * H + gcol] =
                    make_float2(c[mt][ntl][0] + b0, c[mt][ntl][1] + b1);
            if (r0 + 8 < N)
                *(float2*)&C[(size_t)(r0 + 8) * H + gcol] =
                    make_float2(c[mt][ntl][2] + b0, c[mt][ntl][3] + b1);
        }
    }
}

// ---------------- mma.sync bf16 Z GEMM: Zb = bf16(h @ whz + bz) ---------------
__global__ __launch_bounds__(256) void zgemm_kernel(const float* __restrict__ h,
                                                    int N) {
    extern __shared__ unsigned short zsm[];
    unsigned short* As = zsm;                  // [128][BSTRIDE]
    unsigned short* Bs = zsm + 128 * BSTRIDE;  // [n][k]

    int tid = threadIdx.x;
    int wid = tid >> 5, lane = tid & 31;
    int gid = lane >> 2, tig = lane & 3;
    int n0 = blockIdx.x * 128;
    int nt = blockIdx.y * 128;

    for (int idx = tid; idx < 128 * 64; idx += 256) {
        int row = idx >> 6, j = idx & 63;
        float2 f = make_float2(0.f, 0.f);
        if (n0 + row < N) f = *(const float2*)&h[(size_t)(n0 + row) * H + 2 * j];
        *(unsigned*)&As[row * BSTRIDE + 2 * j] = bf16x2_of(f.x, f.y);
    }
    {
        const unsigned* bsrc = &g_whzTb[(size_t)nt * 64];
        for (int idx = tid; idx < 128 * 64; idx += 256) {
            int n = idx >> 6, k2 = idx & 63;
            *(unsigned*)&Bs[n * BSTRIDE + 2 * k2] = bsrc[idx];
        }
    }
    __syncthreads();

    int wm = (wid & 3) * 32;
    int wn = (wid >> 2) * 64;

    float c[2][8][4];
#pragma unroll
    for (int mt = 0; mt < 2; mt++)
#pragma unroll
        for (int ntl = 0; ntl < 8; ntl++)
#pragma unroll
            for (int q = 0; q < 4; q++) c[mt][ntl][q] = 0.f;

#pragma unroll
    for (int k0 = 0; k0 < 128; k0 += 16) {
        uint32_t a[2][4];
#pragma unroll
        for (int mt = 0; mt < 2; mt++) {
            int row = wm + mt * 16;
            a[mt][0] = *(const unsigned*)&As[(row + gid) * BSTRIDE + k0 + 2 * tig];
            a[mt][1] = *(const unsigned*)&As[(row + gid + 8) * BSTRIDE + k0 + 2 * tig];
            a[mt][2] = *(const unsigned*)&As[(row + gid) * BSTRIDE + k0 + 2 * tig + 8];
            a[mt][3] = *(const unsigned*)&As[(row + gid + 8) * BSTRIDE + k0 + 2 * tig + 8];
        }
        uint32_t b[8][2];
#pragma unroll
        for (int ntl = 0; ntl < 8; ntl++) {
            int col = wn + ntl * 8 + gid;
            b[ntl][0] = *(const unsigned*)&Bs[col * BSTRIDE + k0 + 2 * tig];
            b[ntl][1] = *(const unsigned*)&Bs[col * BSTRIDE + k0 + 2 * tig + 8];
        }
#pragma unroll
        for (int mt = 0; mt < 2; mt++)
#pragma unroll
            for (int ntl = 0; ntl < 8; ntl++)
                mma_bf16(c[mt][ntl], a[mt][0], a[mt][1], a[mt][2], a[mt][3],
                         b[ntl][0], b[ntl][1]);
    }

#pragma unroll
    for (int mt = 0; mt < 2; mt++) {
        int r0 = n0 + wm + mt * 16 + gid;
#pragma unroll
        for (int ntl = 0; ntl < 8; ntl++) {
            int gcol = nt + wn + ntl * 8 + 2 * tig;
            float bz0 = g_bz[gcol], bz1 = g_bz[gcol + 1];
            if (r0 < N)
                g_Zb[(size_t)r0 * (ZDIM / 2) + (gcol >> 1)] =
                    bf16x2_of(c[mt][ntl][0] + bz0, c[mt][ntl][1] + bz1);
            if (r0 + 8 < N)
                g_Zb[(size_t)(r0 + 8) * (ZDIM / 2) + (gcol >> 1)] =
                    bf16x2_of(c[mt][ntl][2] + bz0, c[mt][ntl][3] + bz1);
        }
    }
}

// ---------------- P6: warp per node -------------------------------------------
__global__ void p_kernel(int N) {
    int r = (int)((blockIdx.x * blockDim.x + threadIdx.x) >> 5);
    int lane = threadIdx.x & 31;
    if (r >= N) return;
    float4 q = *(const float4*)&g_hq[(size_t)r * H + lane * 4];
#pragma unroll
    for (int u = 0; u < 6; u++) {
        float4 w = *(const float4*)&g_wkr6[u * H + lane * 4];
        float s = q.x * w.x + q.y * w.y + q.z * w.z + q.w * w.w;
#pragma unroll
        for (int o = 16; o; o >>= 1) s += __shfl_xor_sync(0xffffffffu, s, o);
        if (lane == 0) g_P[r * 6 + u] = s;
    }
}

// ---------------- edge prep (sorted order, warp per edge) ---------------------
__global__ void edge_prep_kernel(const float* __restrict__ coord, int E) {
    int p = (int)((blockIdx.x * blockDim.x + threadIdx.x) >> 5);
    int lane = threadIdx.x & 31;
    if (p >= E) return;
    int r = g_rows[p], c = g_cols[p];

    float cdv = 0.f;
    if (lane < 9) cdv = coord[(size_t)r * 9 + lane] - coord[(size_t)c * 9 + lane];
    if (lane < 9) g_cds[(size_t)p * 9 + lane] = cdv;
    float cd[9];
#pragma unroll
    for (int i = 0; i < 9; i++) cd[i] = __shfl_sync(0xffffffffu, cdv, i);

    float radv = 0.f;
    if (lane < 6) {
        int a = sym_a(lane), b = sym_b(lane);
        radv = cd[a * 3] * cd[b * 3] + cd[a * 3 + 1] * cd[b * 3 + 1] +
               cd[a * 3 + 2] * cd[b * 3 + 2];
        g_rads[(size_t)p * 6 + lane] = radv;
    }

    float4 q = *(const float4*)&g_hq[(size_t)r * H + lane * 4];
    float4 k = *(const float4*)&g_hk[(size_t)c * H + lane * 4];
    float ap = q.x * k.x + q.y * k.y + q.z * k.z + q.w * k.w;
    if (lane < 6) ap += radv * g_P[r * 6 + lane];
#pragma unroll
    for (int o = 16; o; o >>= 1) ap += __shfl_xor_sync(0xffffffffu, ap, o);
    if (lane == 0) g_araw[p] = ap;
}

// ---------------- cv kernel: warp per 8 edges (6 folded rad terms) ------------
__global__ __launch_bounds__(256) void cv_kernel(const float* __restrict__ Wc2,
                                                 int E) {
    int lane = threadIdx.x & 31;
    int wg = (int)((blockIdx.x * blockDim.x + threadIdx.x) >> 5);
    int e0 = wg * 8;
    if (e0 >= E) return;

    int cols[8];
    float rr[8];
#pragma unroll
    for (int g = 0; g < 8; g++) {
        int e = e0 + g;
        cols[g] = (e < E) ? g_cols[e] : 0;
        rr[g] = (lane < 6 && e < E) ? g_rads[(size_t)e * 6 + lane] : 0.f;
    }
    float pacc[8][3];
#pragma unroll
    for (int g = 0; g < 8; g++) pacc[g][0] = pacc[g][1] = pacc[g][2] = 0.f;

    for (int jc = 0; jc < 4; jc++) {
        int j0 = jc * 128 + lane * 4;
        float wv[6][4];
#pragma unroll
        for (int u = 0; u < 6; u++) {
            float4 f = *(const float4*)&g_wvc16[u * ZDIM + j0];
            wv[u][0] = f.x; wv[u][1] = f.y; wv[u][2] = f.z; wv[u][3] = f.w;
        }
        float w2[4][3];
#pragma unroll
        for (int jj = 0; jj < 4; jj++)
#pragma unroll
            for (int d = 0; d < 3; d++) w2[jj][d] = Wc2[(j0 + jj) * 3 + d];

#pragma unroll
        for (int g = 0; g < 8; g++) {
            uint2 z = *(const uint2*)&g_Zb[(size_t)cols[g] * (ZDIM / 2) + (j0 >> 1)];
            float x0 = __uint_as_float(z.x << 16);
            float x1 = __uint_as_float(z.x & 0xffff0000u);
            float x2 = __uint_as_float(z.y << 16);
            float x3 = __uint_as_float(z.y & 0xffff0000u);
#pragma unroll
            for (int u = 0; u < 6; u++) {
                float ri = __shfl_sync(0xffffffffu, rr[g], u);
                x0 += ri * wv[u][0];
                x1 += ri * wv[u][1];
                x2 += ri * wv[u][2];
                x3 += ri * wv[u][3];
            }
            float u0 = silu_f(x0), u1 = silu_f(x1), u2 = silu_f(x2), u3 = silu_f(x3);
#pragma unroll
            for (int d = 0; d < 3; d++)
                pacc[g][d] += u0 * w2[0][d] + u1 * w2[1][d] + u2 * w2[2][d] +
                              u3 * w2[3][d];
        }
    }
#pragma unroll
    for (int g = 0; g < 8; g++) {
        float p0 = pacc[g][0], p1 = pacc[g][1], p2 = pacc[g][2];
#pragma unroll
        for (int o = 16; o; o >>= 1) {
            p0 += __shfl_xor_sync(0xffffffffu, p0, o);
            p1 += __shfl_xor_sync(0xffffffffu, p1, o);
            p2 += __shfl_xor_sync(0xffffffffu, p2, o);
        }
        if (lane == 0 && e0 + g < E) {
            g_cvs[(size_t)(e0 + g) * 3 + 0] = p0;
            g_cvs[(size_t)(e0 + g) * 3 + 1] = p1;
            g_cvs[(size_t)(e0 + g) * 3 + 2] = p2;
        }
    }
}

// ---------------- row kernel: softmax + agg + finalize (2x unrolled) ----------
__global__ __launch_bounds__(256) void row_kernel(
    const float* __restrict__ h, const float* __restrict__ coord,
    float* __restrict__ out, float* __restrict__ alpha_out, int N) {
    __shared__ float wvr6_s[6 * H];
    int tid = threadIdx.x, lane = tid & 31, w = tid >> 5;
    for (int i = tid; i < 6 * H; i += 256) wvr6_s[i] = g_wvr6[i];
    __syncthreads();
    int r = blockIdx.x * 8 + w;
    if (r >= N) return;
    int s = g_off[r], e = g_off[r + 1];

    float4 acc = make_float4(0.f, 0.f, 0.f, 0.f);
    float aS = 0.f, cg = 0.f;
    if (e > s) {
        float m = -1e30f;
        for (int p = s + lane; p < e; p += 32) m = fmaxf(m, g_araw[p]);
#pragma unroll
        for (int o = 16; o; o >>= 1)
            m = fmaxf(m, __shfl_xor_sync(0xffffffffu, m, o));
        float den = 0.f;
        for (int p = s + lane; p < e; p += 32) den += __expf(g_araw[p] - m);
#pragma unroll
        for (int o = 16; o; o >>= 1) den += __shfl_xor_sync(0xffffffffu, den, o);
        float invd = 1.f / den;

        int c3 = lane / 3;
        int p = s;
        for (; p + 1 < e; p += 2) {
            int c0 = g_cols[p];
            int c1 = g_cols[p + 1];
            float4 hv0 = *(const float4*)&g_hv[(size_t)c0 * H + lane * 4];
            float4 hv1 = *(const float4*)&g_hv[(size_t)c1 * H + lane * 4];
            float a0 = __expf(g_araw[p] - m) * invd;
            float a1 = __expf(g_araw[p + 1] - m) * invd;
            acc.x += a0 * hv0.x;
            acc.y += a0 * hv0.y;
            acc.z += a0 * hv0.z;
            acc.w += a0 * hv0.w;
            acc.x += a1 * hv1.x;
            acc.y += a1 * hv1.y;
            acc.z += a1 * hv1.z;
            acc.w += a1 * hv1.w;
            if (lane < 6) {
                aS += a0 * g_rads[(size_t)p * 6 + lane];
                aS += a1 * g_rads[(size_t)(p + 1) * 6 + lane];
            }
            if (lane < 9) {
                cg += g_cds[(size_t)p * 9 + lane] *
                      (a0 * g_cvs[(size_t)p * 3 + c3]);
                cg += g_cds[(size_t)(p + 1) * 9 + lane] *
                      (a1 * g_cvs[(size_t)(p + 1) * 3 + c3]);
            }
            if (lane == 0) {
                alpha_out[g_perm[p]] = a0;
                alpha_out[g_perm[p + 1]] = a1;
            }
        }
        if (p < e) {
            int c = g_cols[p];
            float4 hv = *(const float4*)&g_hv[(size_t)c * H + lane * 4];
            float a = __expf(g_araw[p] - m) * invd;
            acc.x += a * hv.x;
            acc.y += a * hv.y;
            acc.z += a * hv.z;
            acc.w += a * hv.w;
            if (lane < 6) aS += a * g_rads[(size_t)p * 6 + lane];
            if (lane < 9)
                cg += g_cds[(size_t)p * 9 + lane] * (a * g_cvs[(size_t)p * 3 + c3]);
            if (lane == 0) alpha_out[g_perm[p]] = a;
        }
#pragma unroll
        for (int u = 0; u < 6; u++) {
            float asu = __shfl_sync(0xffffffffu, aS, u);
            acc.x += asu * wvr6_s[u * H + lane * 4 + 0];
            acc.y += asu * wvr6_s[u * H + lane * 4 + 1];
            acc.z += asu * wvr6_s[u * H + lane * 4 + 2];
            acc.w += asu * wvr6_s[u * H + lane * 4 + 3];
        }
    }
    float4 hh = *(const float4*)&h[(size_t)r * H + lane * 4];
    float4 o4 = make_float4(hh.x + acc.x, hh.y + acc.y, hh.z + acc.z, hh.w + acc.w);
    *(float4*)&out[(size_t)r * H + lane * 4] = o4;
    if (lane < 9) {
        float cgc = fminf(fmaxf(cg, -10.f), 10.f);
        out[(size_t)N * H + (size_t)r * 9 + lane] = coord[(size_t)r * 9 + lane] + cgc;
    }
}

// ---------------- launch -------------------------------------------------------
extern "C" void kernel_launch(void* const* d_in, const int* in_sizes, int n_in,
                              void* d_out, int out_size) {
    const float* h = (const float*)d_in[0];
    const float* coord = (const float*)d_in[1];
    const int* row = (const int*)d_in[2];
    const int* col = (const int*)d_in[3];
    const float* Wq = (const float*)d_in[4];
    const float* bq = (const float*)d_in[5];
    const float* Wkv = (const float*)d_in[6];
    const float* bkv = (const float*)d_in[7];
    const float* Wc1 = (const float*)d_in[8];
    const float* Wc2 = (const float*)d_in[9];
    int N = in_sizes[0] / H;
    int E = in_sizes[2];
    float* out = (float*)d_out;
    float* alpha_out = out + (size_t)N * H + (size_t)N * 9;

    size_t smem_z = (size_t)2 * 128 * BSTRIDE * sizeof(unsigned short);
    size_t smem_q = (size_t)4 * 128 * BSTRIDE * sizeof(unsigned short);
    cudaFuncSetAttribute((const void*)zgemm_kernel,
                         cudaFuncAttributeMaxDynamicSharedMemorySize, (int)smem_z);
    cudaFuncSetAttribute((const void*)qkv_gemm,
                         cudaFuncAttributeMaxDynamicSharedMemorySize, (int)smem_q);

    // CSR build
    zero_kernel<<<(N + 255) / 256, 256>>>(N);
    hist_kernel<<<(E + 255) / 256, 256>>>(row, E);
    scan_kernel<<<1, 1024>>>(N);
    scatter_kernel<<<(E + 255) / 256, 256>>>(row, col, E);

    // weight folds
    fold1_kernel<<<(H * H + 255) / 256, 256>>>(Wkv, bkv);
    fold2_kernel<<<(135 * ZDIM + 255) / 256, 256>>>(Wc1);
    fold3_kernel<<<(3 * 128 * 64 + 255) / 256, 256>>>(Wq);
    fold4_kernel<<<(ZDIM * 64 + 255) / 256, 256>>>();

    // node GEMMs (tensor cores)
    dim3 gq((N + 127) / 128, 3);
    qkv_gemm<<<gq, 256, smem_q>>>(h, bq, N);
    dim3 gz((N + 127) / 128, 4);
    zgemm_kernel<<<gz, 256, smem_z>>>(h, N);

    p_kernel<<<(N * 32 + 255) / 256, 256>>>(N);
    edge_prep_kernel<<<(E * 32 + 255) / 256, 256>>>(coord, E);
    cv_kernel<<<((E + 7) / 8 * 32 + 255) / 256, 256>>>(Wc2, E);
    row_kernel<<<(N + 7) / 8, 256>>>(h, coord, out, alpha_out, N);
}